// round 7
// baseline (speedup 1.0000x reference)
#include <cuda_runtime.h>
#include <math.h>
#include <float.h>

#define S_LEN 2048
#define DIM_  4096
#define NH    32
#define NKV   8
#define HD    128

// Scratch (device globals: allocation-guard safe)
__device__ float g_q[(size_t)S_LEN * DIM_];
__device__ float g_k[(size_t)S_LEN * NKV * HD];
__device__ float g_v[(size_t)S_LEN * NKV * HD];
__device__ float g_attn[(size_t)S_LEN * DIM_];

__device__ __forceinline__ float to_tf32(float x) {
    float r;
    asm("cvt.rna.tf32.f32 %0, %1;" : "=f"(r) : "f"(x));
    return r;
}

__device__ __forceinline__ void mma_tf32(float* c, const float* a, const float* b) {
    asm volatile(
        "mma.sync.aligned.m16n8k8.row.col.f32.tf32.tf32.f32 "
        "{%0,%1,%2,%3}, {%4,%5,%6,%7}, {%8,%9}, {%0,%1,%2,%3};"
        : "+f"(c[0]), "+f"(c[1]), "+f"(c[2]), "+f"(c[3])
        : "r"(__float_as_uint(a[0])), "r"(__float_as_uint(a[1])),
          "r"(__float_as_uint(a[2])), "r"(__float_as_uint(a[3])),
          "r"(__float_as_uint(b[0])), "r"(__float_as_uint(b[1])));
}

// ---------------------------------------------------------------------------
// Split-TF32 (3-mma, ~fp32 accurate) GEMM: C = A @ B, fp32 storage.
// 128x128 tile, BK=16, 256 threads (8 warps 4x2, warp tile 32x64).
// Double-buffered smem: one __syncthreads per iter, LDG staged in regs.
// ---------------------------------------------------------------------------
__global__ __launch_bounds__(256, 2) void mma_gemm(
    const float* __restrict__ A, const float* __restrict__ B,
    float* __restrict__ C, int M, int N, int K)
{
    __shared__ float As[2][16][136];   // [k][m]
    __shared__ float Bs[2][16][136];   // [k][n]

    const int tid  = threadIdx.x;
    const int warp = tid >> 5, lane = tid & 31;
    const int wm = warp >> 1, wn = warp & 1;
    const int m0w = wm * 32, n0w = wn * 64;
    const int bm = blockIdx.y * 128, bn = blockIdx.x * 128;
    const int lr = lane >> 2, lc = lane & 3;

    const int arow = tid >> 1, acol = (tid & 1) * 8;
    const int bkrow = tid >> 5;
    const int bcol = lane * 4;

    float acc[2][8][4];
#pragma unroll
    for (int i = 0; i < 2; i++)
#pragma unroll
        for (int j = 0; j < 8; j++)
#pragma unroll
            for (int r = 0; r < 4; r++) acc[i][j][r] = 0.f;

    const float* Arow = A + (size_t)(bm + arow) * K;
    const float* Bb   = B + bn;

    // Prologue: load tile 0 -> smem buf 0 (raw fp32)
    {
        float4 va0 = *(const float4*)(Arow + acol);
        float4 va1 = *(const float4*)(Arow + acol + 4);
        float4 vb0 = *(const float4*)(Bb + (size_t)bkrow * N + bcol);
        float4 vb1 = *(const float4*)(Bb + (size_t)(bkrow + 8) * N + bcol);
        As[0][acol + 0][arow] = va0.x; As[0][acol + 1][arow] = va0.y;
        As[0][acol + 2][arow] = va0.z; As[0][acol + 3][arow] = va0.w;
        As[0][acol + 4][arow] = va1.x; As[0][acol + 5][arow] = va1.y;
        As[0][acol + 6][arow] = va1.z; As[0][acol + 7][arow] = va1.w;
        *(float4*)&Bs[0][bkrow][bcol]     = vb0;
        *(float4*)&Bs[0][bkrow + 8][bcol] = vb1;
    }
    __syncthreads();

    int buf = 0;
    for (int k0 = 0; k0 < K; k0 += 16) {
        const bool nxt = (k0 + 16 < K);
        float4 na0, na1, nb0, nb1;
        if (nxt) {
            na0 = *(const float4*)(Arow + k0 + 16 + acol);
            na1 = *(const float4*)(Arow + k0 + 16 + acol + 4);
            nb0 = *(const float4*)(Bb + (size_t)(k0 + 16 + bkrow) * N + bcol);
            nb1 = *(const float4*)(Bb + (size_t)(k0 + 16 + bkrow + 8) * N + bcol);
        }

#pragma unroll
        for (int ks = 0; ks < 2; ks++) {
            const int kb = ks * 8;
            float ahi[2][4], alo[2][4];
#pragma unroll
            for (int im = 0; im < 2; im++) {
                const int m0 = m0w + im * 16 + lr;
                float r0 = As[buf][kb + lc][m0];
                float r1 = As[buf][kb + lc][m0 + 8];
                float r2 = As[buf][kb + 4 + lc][m0];
                float r3 = As[buf][kb + 4 + lc][m0 + 8];
                ahi[im][0] = to_tf32(r0); alo[im][0] = to_tf32(r0 - ahi[im][0]);
                ahi[im][1] = to_tf32(r1); alo[im][1] = to_tf32(r1 - ahi[im][1]);
                ahi[im][2] = to_tf32(r2); alo[im][2] = to_tf32(r2 - ahi[im][2]);
                ahi[im][3] = to_tf32(r3); alo[im][3] = to_tf32(r3 - ahi[im][3]);
            }
#pragma unroll
            for (int in_ = 0; in_ < 8; in_++) {
                const int n0 = n0w + in_ * 8 + lr;
                float q0 = Bs[buf][kb + lc][n0];
                float q1 = Bs[buf][kb + 4 + lc][n0];
                float bh[2] = {to_tf32(q0), to_tf32(q1)};
                float bl[2] = {to_tf32(q0 - bh[0]), to_tf32(q1 - bh[1])};
                mma_tf32(acc[0][in_], ahi[0], bh);
                mma_tf32(acc[1][in_], ahi[1], bh);
                mma_tf32(acc[0][in_], ahi[0], bl);
                mma_tf32(acc[1][in_], ahi[1], bl);
                mma_tf32(acc[0][in_], alo[0], bh);
                mma_tf32(acc[1][in_], alo[1], bh);
            }
        }

        if (nxt) {
            const int nb = buf ^ 1;
            As[nb][acol + 0][arow] = na0.x; As[nb][acol + 1][arow] = na0.y;
            As[nb][acol + 2][arow] = na0.z; As[nb][acol + 3][arow] = na0.w;
            As[nb][acol + 4][arow] = na1.x; As[nb][acol + 5][arow] = na1.y;
            As[nb][acol + 6][arow] = na1.z; As[nb][acol + 7][arow] = na1.w;
            *(float4*)&Bs[nb][bkrow][bcol]     = nb0;
            *(float4*)&Bs[nb][bkrow + 8][bcol] = nb1;
        }
        __syncthreads();
        buf ^= 1;
    }

    float* Cb = C + (size_t)(bm + m0w + lr) * N + bn + n0w + lc * 2;
#pragma unroll
    for (int im = 0; im < 2; im++)
#pragma unroll
        for (int in_ = 0; in_ < 8; in_++) {
            float* p = Cb + (size_t)(im * 16) * N + in_ * 8;
            *(float2*)p = make_float2(acc[im][in_][0], acc[im][in_][1]);
            *(float2*)(p + (size_t)8 * N) = make_float2(acc[im][in_][2], acc[im][in_][3]);
        }
}

// ---------------------------------------------------------------------------
// RoPE: interleaved pairs (2i, 2i+1), cos/sin are [S, HD/2]
// ---------------------------------------------------------------------------
__global__ void rope_kernel(float* __restrict__ t, const float* __restrict__ cosv,
                            const float* __restrict__ sinv, int nheads, int total)
{
    int idx = blockIdx.x * blockDim.x + threadIdx.x;
    if (idx >= total) return;
    int pair = idx & 63;
    int h    = (idx >> 6) % nheads;
    int seq  = idx / (64 * nheads);
    float c = cosv[seq * 64 + pair];
    float s = sinv[seq * 64 + pair];
    float* p = t + (size_t)seq * nheads * HD + h * HD + pair * 2;
    float2 v = *(float2*)p;
    float re = v.x, im = v.y;
    v.x = re * c - im * s;
    v.y = re * s + im * c;
    *(float2*)p = v;
}

// ---------------------------------------------------------------------------
// Tensor-core flash attention (causal, GQA kv = h/4).
// 128-query CTA tile, 64-key tiles, 256 threads (8 warps, warp = m16 x n64).
// QK^T: split-TF32 (3-mma) with K pre-split into Khi/Klo smem (~fp32 exact).
// PV: 1x TF32 (positive-weight average -> small error).
// Smem strides chosen conflict-free for each fragment pattern.
// ---------------------------------------------------------------------------
__global__ __launch_bounds__(256) void flash_attn_mma(
    const float* __restrict__ Qg, const float* __restrict__ Kg,
    const float* __restrict__ Vg, float* __restrict__ Og)
{
    extern __shared__ float sm[];
    float* Qs  = sm;                   // [128][132] raw fp32
    float* Khi = Qs  + 128 * 132;      // [64][132] tf32 hi
    float* Klo = Khi + 64 * 132;       // [64][132] tf32 lo
    float* Vs  = Klo + 64 * 132;       // [64][136] tf32
    float* Ps  = Vs  + 64 * 136;       // [128][68] tf32

    const int qt  = (int)gridDim.x - 1 - (int)blockIdx.x;  // heavy tiles first
    const int h   = blockIdx.y;
    const int kvh = h >> 2;
    const int tid = threadIdx.x;
    const int warp = tid >> 5, lane = tid & 31;
    const int lr = lane >> 2, lc = lane & 3;
    const int m0 = warp * 16;
    const float scale = 0.08838834764831845f;  // 1/sqrt(128)

    // Load Q tile (raw fp32), rows qt*128..+127
#pragma unroll
    for (int it = 0; it < 16; it++) {
        int idx = it * 256 + tid;
        int q = idx >> 5, d4 = (idx & 31) * 4;
        float4 v = *(const float4*)(Qg + (size_t)(qt * 128 + q) * DIM_ + h * HD + d4);
        *(float4*)(Qs + q * 132 + d4) = v;
    }

    float o[16][4];
#pragma unroll
    for (int i = 0; i < 16; i++)
#pragma unroll
        for (int j = 0; j < 4; j++) o[i][j] = 0.f;
    float mrow0 = -1e30f, mrow1 = -1e30f, lrow0 = 0.f, lrow1 = 0.f;

    const int nkt = 2 * qt + 2;
    for (int kt = 0; kt < nkt; kt++) {
        __syncthreads();
        // Load K tile -> hi/lo tf32 split; V tile -> tf32
#pragma unroll
        for (int it = 0; it < 8; it++) {
            int idx = it * 256 + tid;
            int kr = idx >> 5, d4 = (idx & 31) * 4;
            size_t off = (size_t)(kt * 64 + kr) * (NKV * HD) + kvh * HD + d4;
            float4 kv = *(const float4*)(Kg + off);
            float4 hi, lo;
            hi.x = to_tf32(kv.x); lo.x = to_tf32(kv.x - hi.x);
            hi.y = to_tf32(kv.y); lo.y = to_tf32(kv.y - hi.y);
            hi.z = to_tf32(kv.z); lo.z = to_tf32(kv.z - hi.z);
            hi.w = to_tf32(kv.w); lo.w = to_tf32(kv.w - hi.w);
            *(float4*)(Khi + kr * 132 + d4) = hi;
            *(float4*)(Klo + kr * 132 + d4) = lo;
            float4 vv = *(const float4*)(Vg + off);
            vv.x = to_tf32(vv.x); vv.y = to_tf32(vv.y);
            vv.z = to_tf32(vv.z); vv.w = to_tf32(vv.w);
            *(float4*)(Vs + kr * 136 + d4) = vv;
        }
        __syncthreads();

        // Skip warps whose whole 16-row tile is strictly above the diagonal
        if (kt * 64 > qt * 128 + m0 + 15) continue;

        // S = Q K^T (m16 x n64 x k128), split-TF32
        float s[8][4];
#pragma unroll
        for (int nt = 0; nt < 8; nt++)
#pragma unroll
            for (int j = 0; j < 4; j++) s[nt][j] = 0.f;

#pragma unroll 2
        for (int kk = 0; kk < 16; kk++) {
            const int kb = kk * 8;
            float r0 = Qs[(m0 + lr) * 132 + kb + lc];
            float r1 = Qs[(m0 + lr + 8) * 132 + kb + lc];
            float r2 = Qs[(m0 + lr) * 132 + kb + lc + 4];
            float r3 = Qs[(m0 + lr + 8) * 132 + kb + lc + 4];
            float ahi[4] = {to_tf32(r0), to_tf32(r1), to_tf32(r2), to_tf32(r3)};
            float alo[4] = {to_tf32(r0 - ahi[0]), to_tf32(r1 - ahi[1]),
                            to_tf32(r2 - ahi[2]), to_tf32(r3 - ahi[3])};
#pragma unroll
            for (int nt = 0; nt < 8; nt++) {
                const int n0 = (nt * 8 + lr) * 132 + kb + lc;
                float bh[2] = {Khi[n0], Khi[n0 + 4]};
                float bl[2] = {Klo[n0], Klo[n0 + 4]};
                mma_tf32(s[nt], ahi, bh);
                mma_tf32(s[nt], ahi, bl);
                mma_tf32(s[nt], alo, bh);
            }
        }

        // Scale + causal mask (only the two diagonal-overlapping tiles)
        const int r0g = qt * 128 + m0 + lr, r1g = r0g + 8;
        const bool diag = (kt >= 2 * qt);
        float mx0 = -1e30f, mx1 = -1e30f;
#pragma unroll
        for (int nt = 0; nt < 8; nt++) {
            int c = kt * 64 + nt * 8 + lc * 2;
            float v0 = s[nt][0] * scale, v1 = s[nt][1] * scale;
            float v2 = s[nt][2] * scale, v3 = s[nt][3] * scale;
            if (diag) {
                if (c     > r0g) v0 = -1e30f;
                if (c + 1 > r0g) v1 = -1e30f;
                if (c     > r1g) v2 = -1e30f;
                if (c + 1 > r1g) v3 = -1e30f;
            }
            s[nt][0] = v0; s[nt][1] = v1; s[nt][2] = v2; s[nt][3] = v3;
            mx0 = fmaxf(mx0, fmaxf(v0, v1));
            mx1 = fmaxf(mx1, fmaxf(v2, v3));
        }
        mx0 = fmaxf(mx0, __shfl_xor_sync(0xffffffffu, mx0, 1));
        mx0 = fmaxf(mx0, __shfl_xor_sync(0xffffffffu, mx0, 2));
        mx1 = fmaxf(mx1, __shfl_xor_sync(0xffffffffu, mx1, 1));
        mx1 = fmaxf(mx1, __shfl_xor_sync(0xffffffffu, mx1, 2));

        const float mt0 = fmaxf(mrow0, mx0), mt1 = fmaxf(mrow1, mx1);
        const float fac0 = __expf(mrow0 - mt0), fac1 = __expf(mrow1 - mt1);

        float sum0 = 0.f, sum1 = 0.f;
#pragma unroll
        for (int nt = 0; nt < 8; nt++) {
            float p0 = __expf(s[nt][0] - mt0), p1 = __expf(s[nt][1] - mt0);
            float p2 = __expf(s[nt][2] - mt1), p3 = __expf(s[nt][3] - mt1);
            sum0 += p0 + p1; sum1 += p2 + p3;
            *(float2*)(Ps + (m0 + lr) * 68 + nt * 8 + lc * 2) =
                make_float2(to_tf32(p0), to_tf32(p1));
            *(float2*)(Ps + (m0 + lr + 8) * 68 + nt * 8 + lc * 2) =
                make_float2(to_tf32(p2), to_tf32(p3));
        }
        sum0 += __shfl_xor_sync(0xffffffffu, sum0, 1);
        sum0 += __shfl_xor_sync(0xffffffffu, sum0, 2);
        sum1 += __shfl_xor_sync(0xffffffffu, sum1, 1);
        sum1 += __shfl_xor_sync(0xffffffffu, sum1, 2);

        lrow0 = lrow0 * fac0 + sum0;
        lrow1 = lrow1 * fac1 + sum1;
        mrow0 = mt0; mrow1 = mt1;
#pragma unroll
        for (int nt = 0; nt < 16; nt++) {
            o[nt][0] *= fac0; o[nt][1] *= fac0;
            o[nt][2] *= fac1; o[nt][3] *= fac1;
        }
        __syncwarp();   // Ps rows are warp-private; make stores visible

        // O += P @ V (m16 x n128 x k64), 1x TF32
#pragma unroll 2
        for (int kk = 0; kk < 8; kk++) {
            const int kb = kk * 8;
            float a[4] = {Ps[(m0 + lr) * 68 + kb + lc],
                          Ps[(m0 + lr + 8) * 68 + kb + lc],
                          Ps[(m0 + lr) * 68 + kb + lc + 4],
                          Ps[(m0 + lr + 8) * 68 + kb + lc + 4]};
#pragma unroll
            for (int nt = 0; nt < 16; nt++) {
                float b[2] = {Vs[(kb + lc) * 136 + nt * 8 + lr],
                              Vs[(kb + lc + 4) * 136 + nt * 8 + lr]};
                mma_tf32(o[nt], a, b);
            }
        }
    }

    // Epilogue: normalize, write [s][h*128+d]
    const float inv0 = 1.f / lrow0, inv1 = 1.f / lrow1;
    float* base0 = Og + (size_t)(qt * 128 + m0 + lr) * DIM_ + h * HD;
    float* base1 = base0 + (size_t)8 * DIM_;
#pragma unroll
    for (int nt = 0; nt < 16; nt++) {
        *(float2*)(base0 + nt * 8 + lc * 2) =
            make_float2(o[nt][0] * inv0, o[nt][1] * inv0);
        *(float2*)(base1 + nt * 8 + lc * 2) =
            make_float2(o[nt][2] * inv1, o[nt][3] * inv1);
    }
}

// ---------------------------------------------------------------------------
// Launcher
// ---------------------------------------------------------------------------
static const int FLASH_SMEM =
    (128 * 132 + 64 * 132 + 64 * 132 + 64 * 136 + 128 * 68) * 4;  // 204800 B

extern "C" void kernel_launch(void* const* d_in, const int* in_sizes, int n_in,
                              void* d_out, int out_size)
{
    const float* x  = (const float*)d_in[0];
    const float* wq = (const float*)d_in[1];
    const float* wk = (const float*)d_in[2];
    const float* wv = (const float*)d_in[3];
    const float* wo = (const float*)d_in[4];
    const float* fc = (const float*)d_in[5];
    const float* fs = (const float*)d_in[6];
    float* out = (float*)d_out;

    float *q, *k, *v, *attn;
    cudaGetSymbolAddress((void**)&q,    g_q);
    cudaGetSymbolAddress((void**)&k,    g_k);
    cudaGetSymbolAddress((void**)&v,    g_v);
    cudaGetSymbolAddress((void**)&attn, g_attn);

    cudaFuncSetAttribute(flash_attn_mma,
                         cudaFuncAttributeMaxDynamicSharedMemorySize, FLASH_SMEM);

    dim3 blk(256);
    // Projections (split-TF32 tensor cores, ~fp32 accurate)
    mma_gemm<<<dim3(DIM_ / 128,       S_LEN / 128), blk>>>(x, wq, q, S_LEN, DIM_,     DIM_);
    mma_gemm<<<dim3((NKV * HD) / 128, S_LEN / 128), blk>>>(x, wk, k, S_LEN, NKV * HD, DIM_);
    mma_gemm<<<dim3((NKV * HD) / 128, S_LEN / 128), blk>>>(x, wv, v, S_LEN, NKV * HD, DIM_);
    // RoPE
    int totq = S_LEN * NH * 64;
    rope_kernel<<<(totq + 255) / 256, 256>>>(q, fc, fs, NH, totq);
    int totk = S_LEN * NKV * 64;
    rope_kernel<<<(totk + 255) / 256, 256>>>(k, fc, fs, NKV, totk);
    // Attention (tensor cores)
    flash_attn_mma<<<dim3(S_LEN / 128, NH), blk, FLASH_SMEM>>>(q, k, v, attn);
    // Output projection
    mma_gemm<<<dim3(DIM_ / 128, S_LEN / 128), blk>>>(attn, wo, out, S_LEN, DIM_, DIM_);
}

// round 10
// speedup vs baseline: 1.5334x; 1.5334x over previous
#include <cuda_runtime.h>
#include <cuda_bf16.h>
#include <math.h>
#include <float.h>
#include <stdint.h>

#define S_LEN 2048
#define DIM_  4096
#define NH    32
#define NKV   8
#define HD    128

// ---------------------------------------------------------------------------
// Device-global scratch (allocation-guard safe)
// ---------------------------------------------------------------------------
__device__ float g_q[(size_t)S_LEN * DIM_];
__device__ float g_k[(size_t)S_LEN * NKV * HD];
__device__ float g_v[(size_t)S_LEN * NKV * HD];

__device__ __nv_bfloat16 g_xhi[(size_t)S_LEN * DIM_];
__device__ __nv_bfloat16 g_xlo[(size_t)S_LEN * DIM_];
__device__ __nv_bfloat16 g_ahi[(size_t)S_LEN * DIM_];
__device__ __nv_bfloat16 g_alo[(size_t)S_LEN * DIM_];

__device__ __nv_bfloat16 g_wqh[(size_t)DIM_ * DIM_];
__device__ __nv_bfloat16 g_wql[(size_t)DIM_ * DIM_];
__device__ __nv_bfloat16 g_wkh[(size_t)(NKV * HD) * DIM_];
__device__ __nv_bfloat16 g_wkl[(size_t)(NKV * HD) * DIM_];
__device__ __nv_bfloat16 g_wvh[(size_t)(NKV * HD) * DIM_];
__device__ __nv_bfloat16 g_wvl[(size_t)(NKV * HD) * DIM_];
__device__ __nv_bfloat16 g_woh[(size_t)DIM_ * DIM_];
__device__ __nv_bfloat16 g_wol[(size_t)DIM_ * DIM_];

// ---------------------------------------------------------------------------
// Helpers
// ---------------------------------------------------------------------------
__device__ __forceinline__ void mma_bf16(float* c, const uint32_t* a,
                                         uint32_t b0, uint32_t b1) {
    asm volatile(
        "mma.sync.aligned.m16n8k16.row.col.f32.bf16.bf16.f32 "
        "{%0,%1,%2,%3}, {%4,%5,%6,%7}, {%8,%9}, {%0,%1,%2,%3};"
        : "+f"(c[0]), "+f"(c[1]), "+f"(c[2]), "+f"(c[3])
        : "r"(a[0]), "r"(a[1]), "r"(a[2]), "r"(a[3]), "r"(b0), "r"(b1));
}

__device__ __forceinline__ void split_pair(float x, float y,
                                           uint32_t& h, uint32_t& l) {
    __nv_bfloat16 hx = __float2bfloat16_rn(x), hy = __float2bfloat16_rn(y);
    __nv_bfloat162 hp; hp.x = hx; hp.y = hy;
    __nv_bfloat162 lp;
    lp.x = __float2bfloat16_rn(x - __bfloat162float(hx));
    lp.y = __float2bfloat16_rn(y - __bfloat162float(hy));
    h = *(uint32_t*)&hp;
    l = *(uint32_t*)&lp;
}

__device__ __forceinline__ void cp16(uint32_t saddr, const void* g) {
    asm volatile("cp.async.ca.shared.global [%0], [%1], 16;"
                 :: "r"(saddr), "l"(g));
}
__device__ __forceinline__ void cp_commit() {
    asm volatile("cp.async.commit_group;");
}
template <int N> __device__ __forceinline__ void cp_wait() {
    asm volatile("cp.async.wait_group %0;" :: "n"(N));
}

// ---------------------------------------------------------------------------
// Prep: elementwise fp32 -> bf16 hi/lo split (for x)
// ---------------------------------------------------------------------------
__global__ void split_kernel(const float* __restrict__ in,
                             __nv_bfloat16* __restrict__ hi,
                             __nv_bfloat16* __restrict__ lo, int n) {
    int i = blockIdx.x * blockDim.x + threadIdx.x;
    if (i >= n) return;
    float v = in[i];
    __nv_bfloat16 h = __float2bfloat16_rn(v);
    hi[i] = h;
    lo[i] = __float2bfloat16_rn(v - __bfloat162float(h));
}

// ---------------------------------------------------------------------------
// Prep: weight transpose + split. w [K][N] fp32 -> hi/lo [N][K] bf16.
// ---------------------------------------------------------------------------
__global__ void wsplit_kernel(const float* __restrict__ w,
                              __nv_bfloat16* __restrict__ hi,
                              __nv_bfloat16* __restrict__ lo, int K, int N) {
    __shared__ float t[32][33];
    const int n0 = blockIdx.x * 32, k0 = blockIdx.y * 32;
    const int tx = threadIdx.x, ty = threadIdx.y;
#pragma unroll
    for (int j = 0; j < 4; j++)
        t[tx][ty + 8 * j] = w[(size_t)(k0 + ty + 8 * j) * N + n0 + tx];
    __syncthreads();
#pragma unroll
    for (int j = 0; j < 4; j++) {
        float v = t[ty + 8 * j][tx];
        __nv_bfloat16 h = __float2bfloat16_rn(v);
        size_t o = (size_t)(n0 + ty + 8 * j) * K + k0 + tx;
        hi[o] = h;
        lo[o] = __float2bfloat16_rn(v - __bfloat162float(h));
    }
}

// ---------------------------------------------------------------------------
// bf16x3 GEMM: C[M][N] fp32 = (Ahi+Alo)[M][K] @ (Bhi+Blo)[N][K]^T
// 128x128 tile, BK=32, 256 threads (8 warps 4x2, warp tile 32x64).
// All planes cp.async double-buffered. 3-mma split (hi*hi + hi*lo + lo*hi).
// Smem pair-word stride 20 (== 4 mod 32): conflict-free fragment LDS.
// ---------------------------------------------------------------------------
#define GPS 2560   // plane words per buffer: 128 rows * 20
__global__ __launch_bounds__(256, 2) void gemm_bf16x3(
    const __nv_bfloat16* __restrict__ Ahi_g, const __nv_bfloat16* __restrict__ Alo_g,
    const __nv_bfloat16* __restrict__ Bhi_g, const __nv_bfloat16* __restrict__ Blo_g,
    float* __restrict__ C, int M, int N, int K)
{
    extern __shared__ uint32_t smg[];
    uint32_t* Ah = smg;
    uint32_t* Al = Ah + 2 * GPS;
    uint32_t* Bh = Al + 2 * GPS;
    uint32_t* Bl = Bh + 2 * GPS;

    const int tid = threadIdx.x;
    const int warp = tid >> 5, lane = tid & 31;
    const int wm = warp >> 1, wn = warp & 1;
    const int m0w = wm * 32, n0w = wn * 64;
    const int bm = blockIdx.y * 128, bn = blockIdx.x * 128;
    const int lr = lane >> 2, lc = lane & 3;

    const int c0i = tid * 2, c1i = tid * 2 + 1;
    const int r0 = c0i >> 2, s0 = c0i & 3;
    const int r1 = c1i >> 2, s1 = c1i & 3;

    float acc[2][8][4];
#pragma unroll
    for (int i = 0; i < 2; i++)
#pragma unroll
        for (int j = 0; j < 8; j++)
#pragma unroll
            for (int r = 0; r < 4; r++) acc[i][j][r] = 0.f;

    auto issue = [&](int buf, int k0) {
        uint32_t sa;
        sa = (uint32_t)__cvta_generic_to_shared(Ah + buf * GPS + r0 * 20 + s0 * 4);
        cp16(sa, Ahi_g + (size_t)(bm + r0) * K + k0 + s0 * 8);
        sa = (uint32_t)__cvta_generic_to_shared(Ah + buf * GPS + r1 * 20 + s1 * 4);
        cp16(sa, Ahi_g + (size_t)(bm + r1) * K + k0 + s1 * 8);
        sa = (uint32_t)__cvta_generic_to_shared(Al + buf * GPS + r0 * 20 + s0 * 4);
        cp16(sa, Alo_g + (size_t)(bm + r0) * K + k0 + s0 * 8);
        sa = (uint32_t)__cvta_generic_to_shared(Al + buf * GPS + r1 * 20 + s1 * 4);
        cp16(sa, Alo_g + (size_t)(bm + r1) * K + k0 + s1 * 8);
        sa = (uint32_t)__cvta_generic_to_shared(Bh + buf * GPS + r0 * 20 + s0 * 4);
        cp16(sa, Bhi_g + (size_t)(bn + r0) * K + k0 + s0 * 8);
        sa = (uint32_t)__cvta_generic_to_shared(Bh + buf * GPS + r1 * 20 + s1 * 4);
        cp16(sa, Bhi_g + (size_t)(bn + r1) * K + k0 + s1 * 8);
        sa = (uint32_t)__cvta_generic_to_shared(Bl + buf * GPS + r0 * 20 + s0 * 4);
        cp16(sa, Blo_g + (size_t)(bn + r0) * K + k0 + s0 * 8);
        sa = (uint32_t)__cvta_generic_to_shared(Bl + buf * GPS + r1 * 20 + s1 * 4);
        cp16(sa, Blo_g + (size_t)(bn + r1) * K + k0 + s1 * 8);
    };

    issue(0, 0);
    cp_commit();

    const int niter = K / 32;
    int buf = 0;
    for (int it = 0; it < niter; it++) {
        if (it + 1 < niter) {
            issue(buf ^ 1, (it + 1) * 32);
            cp_commit();
            cp_wait<1>();
        } else {
            cp_wait<0>();
        }
        __syncthreads();

        const uint32_t* Ahb = Ah + buf * GPS;
        const uint32_t* Alb = Al + buf * GPS;
        const uint32_t* Bhb = Bh + buf * GPS;
        const uint32_t* Blb = Bl + buf * GPS;

#pragma unroll
        for (int s = 0; s < 2; s++) {
            uint32_t ah[2][4], al[2][4];
#pragma unroll
            for (int im = 0; im < 2; im++) {
                const int base = (m0w + im * 16 + lr) * 20 + s * 8;
                ah[im][0] = Ahb[base + lc];
                ah[im][1] = Ahb[base + 160 + lc];
                ah[im][2] = Ahb[base + lc + 4];
                ah[im][3] = Ahb[base + 160 + lc + 4];
                al[im][0] = Alb[base + lc];
                al[im][1] = Alb[base + 160 + lc];
                al[im][2] = Alb[base + lc + 4];
                al[im][3] = Alb[base + 160 + lc + 4];
            }
#pragma unroll
            for (int nt = 0; nt < 8; nt++) {
                const int nb = (n0w + nt * 8 + lr) * 20 + s * 8;
                uint32_t bh0 = Bhb[nb + lc], bh1 = Bhb[nb + lc + 4];
                uint32_t bl0 = Blb[nb + lc], bl1 = Blb[nb + lc + 4];
                mma_bf16(acc[0][nt], ah[0], bh0, bh1);
                mma_bf16(acc[1][nt], ah[1], bh0, bh1);
                mma_bf16(acc[0][nt], ah[0], bl0, bl1);
                mma_bf16(acc[1][nt], ah[1], bl0, bl1);
                mma_bf16(acc[0][nt], al[0], bh0, bh1);
                mma_bf16(acc[1][nt], al[1], bh0, bh1);
            }
        }
        __syncthreads();
        buf ^= 1;
    }

    float* Cb = C + (size_t)(bm + m0w + lr) * N + bn + n0w + lc * 2;
#pragma unroll
    for (int im = 0; im < 2; im++)
#pragma unroll
        for (int nt = 0; nt < 8; nt++) {
            float* p = Cb + (size_t)(im * 16) * N + nt * 8;
            *(float2*)p = make_float2(acc[im][nt][0], acc[im][nt][1]);
            *(float2*)(p + (size_t)8 * N) = make_float2(acc[im][nt][2], acc[im][nt][3]);
        }
}

// ---------------------------------------------------------------------------
// RoPE: interleaved pairs (2i, 2i+1), cos/sin are [S, HD/2]
// ---------------------------------------------------------------------------
__global__ void rope_kernel(float* __restrict__ t, const float* __restrict__ cosv,
                            const float* __restrict__ sinv, int nheads, int total)
{
    int idx = blockIdx.x * blockDim.x + threadIdx.x;
    if (idx >= total) return;
    int pair = idx & 63;
    int h    = (idx >> 6) % nheads;
    int seq  = idx / (64 * nheads);
    float c = cosv[seq * 64 + pair];
    float s = sinv[seq * 64 + pair];
    float* p = t + (size_t)seq * nheads * HD + h * HD + pair * 2;
    float2 v = *(float2*)p;
    float re = v.x, im = v.y;
    v.x = re * c - im * s;
    v.y = re * s + im * c;
    *(float2*)p = v;
}

// ---------------------------------------------------------------------------
// bf16x3 flash attention (causal, GQA kv = h/4).
// 128-query CTA tile, 64-key tiles, 256 threads (8 warps, warp = m16 x n64..128).
// QK^T and PV both split-bf16 3-mma. Writes attn as bf16 hi/lo planes.
// Pair-word strides: Q/K = 68, V^T/P = 36 (both == 4 mod 32: conflict-free).
// ---------------------------------------------------------------------------
__global__ __launch_bounds__(256) void flash_attn_bf16(
    const float* __restrict__ Qg, const float* __restrict__ Kg,
    const float* __restrict__ Vg,
    __nv_bfloat16* __restrict__ AHg, __nv_bfloat16* __restrict__ ALg)
{
    extern __shared__ uint32_t smf[];
    uint32_t* Qh = smf;              // [128][68]
    uint32_t* Ql = Qh + 128 * 68;
    uint32_t* Kh = Ql + 128 * 68;    // [64][68]
    uint32_t* Kl = Kh + 64 * 68;
    uint32_t* Vh = Kl + 64 * 68;     // V^T: [128 d][36] (32 key-pairs)
    uint32_t* Vl = Vh + 128 * 36;
    uint32_t* Ph = Vl + 128 * 36;    // [128 q][36]
    uint32_t* Pl = Ph + 128 * 36;
    __nv_bfloat16* Vh16 = (__nv_bfloat16*)Vh;
    __nv_bfloat16* Vl16 = (__nv_bfloat16*)Vl;

    const int qt  = (int)gridDim.x - 1 - (int)blockIdx.x;  // heavy tiles first
    const int h   = blockIdx.y;
    const int kvh = h >> 2;
    const int tid = threadIdx.x;
    const int warp = tid >> 5, lane = tid & 31;
    const int lr = lane >> 2, lc = lane & 3;
    const int m0 = warp * 16;
    const float scale = 0.08838834764831845f;  // 1/sqrt(128)

    // Load + split Q tile
#pragma unroll
    for (int it = 0; it < 16; it++) {
        int idx = it * 256 + tid;
        int q = idx >> 5, d4 = (idx & 31) * 4;
        float4 v = *(const float4*)(Qg + (size_t)(qt * 128 + q) * DIM_ + h * HD + d4);
        uint32_t h0, l0, h1, l1;
        split_pair(v.x, v.y, h0, l0);
        split_pair(v.z, v.w, h1, l1);
        Qh[q * 68 + d4 / 2]     = h0;
        Qh[q * 68 + d4 / 2 + 1] = h1;
        Ql[q * 68 + d4 / 2]     = l0;
        Ql[q * 68 + d4 / 2 + 1] = l1;
    }

    float o[16][4];
#pragma unroll
    for (int i = 0; i < 16; i++)
#pragma unroll
        for (int j = 0; j < 4; j++) o[i][j] = 0.f;
    float mrow0 = -1e30f, mrow1 = -1e30f, lrow0 = 0.f, lrow1 = 0.f;

    const int nkt = 2 * qt + 2;
    for (int kt = 0; kt < nkt; kt++) {
        __syncthreads();
        // K tile -> hi/lo planes; V tile -> transposed hi/lo planes
#pragma unroll
        for (int it = 0; it < 8; it++) {
            int idx = it * 256 + tid;
            int kr = idx >> 5, d4 = (idx & 31) * 4;
            size_t off = (size_t)(kt * 64 + kr) * (NKV * HD) + kvh * HD + d4;
            float4 kv = *(const float4*)(Kg + off);
            uint32_t h0, l0, h1, l1;
            split_pair(kv.x, kv.y, h0, l0);
            split_pair(kv.z, kv.w, h1, l1);
            Kh[kr * 68 + d4 / 2]     = h0;
            Kh[kr * 68 + d4 / 2 + 1] = h1;
            Kl[kr * 68 + d4 / 2]     = l0;
            Kl[kr * 68 + d4 / 2 + 1] = l1;

            float4 vv = *(const float4*)(Vg + off);
            const int kp = kr >> 1, kh_ = kr & 1;
#pragma unroll
            for (int j = 0; j < 4; j++) {
                float x = (&vv.x)[j];
                __nv_bfloat16 hb = __float2bfloat16_rn(x);
                Vh16[((d4 + j) * 36 + kp) * 2 + kh_] = hb;
                Vl16[((d4 + j) * 36 + kp) * 2 + kh_] =
                    __float2bfloat16_rn(x - __bfloat162float(hb));
            }
        }
        __syncthreads();

        // Skip warps whose whole 16-row tile is strictly above the diagonal
        if (kt * 64 > qt * 128 + m0 + 15) continue;

        // ---- S = Q K^T (m16 x n64 x k128), split-bf16 ----
        float s[8][4];
#pragma unroll
        for (int nt = 0; nt < 8; nt++)
#pragma unroll
            for (int j = 0; j < 4; j++) s[nt][j] = 0.f;

#pragma unroll
        for (int ks = 0; ks < 8; ks++) {
            uint32_t ah[4], al[4];
            const int ab  = (m0 + lr) * 68 + ks * 8;
            const int ab8 = ab + 8 * 68;
            ah[0] = Qh[ab + lc];     ah[1] = Qh[ab8 + lc];
            ah[2] = Qh[ab + lc + 4]; ah[3] = Qh[ab8 + lc + 4];
            al[0] = Ql[ab + lc];     al[1] = Ql[ab8 + lc];
            al[2] = Ql[ab + lc + 4]; al[3] = Ql[ab8 + lc + 4];
#pragma unroll
            for (int nt = 0; nt < 8; nt++) {
                const int nb = (nt * 8 + lr) * 68 + ks * 8;
                uint32_t bh0 = Kh[nb + lc], bh1 = Kh[nb + lc + 4];
                uint32_t bl0 = Kl[nb + lc], bl1 = Kl[nb + lc + 4];
                mma_bf16(s[nt], ah, bh0, bh1);
                mma_bf16(s[nt], ah, bl0, bl1);
                mma_bf16(s[nt], al, bh0, bh1);
            }
        }

        // ---- Scale + causal mask ----
        const int r0g = qt * 128 + m0 + lr, r1g = r0g + 8;
        const bool diag = (kt >= 2 * qt);
        float mx0 = -1e30f, mx1 = -1e30f;
#pragma unroll
        for (int nt = 0; nt < 8; nt++) {
            int c = kt * 64 + nt * 8 + lc * 2;
            float v0 = s[nt][0] * scale, v1 = s[nt][1] * scale;
            float v2 = s[nt][2] * scale, v3 = s[nt][3] * scale;
            if (diag) {
                if (c     > r0g) v0 = -1e30f;
                if (c + 1 > r0g) v1 = -1e30f;
                if (c     > r1g) v2 = -1e30f;
                if (c + 1 > r1g) v3 = -1e30f;
            }
            s[nt][0] = v0; s[nt][1] = v1; s[nt][2] = v2; s[nt][3] = v3;
            mx0 = fmaxf(mx0, fmaxf(v0, v1));
            mx1 = fmaxf(mx1, fmaxf(v2, v3));
        }
        mx0 = fmaxf(mx0, __shfl_xor_sync(0xffffffffu, mx0, 1));
        mx0 = fmaxf(mx0, __shfl_xor_sync(0xffffffffu, mx0, 2));
        mx1 = fmaxf(mx1, __shfl_xor_sync(0xffffffffu, mx1, 1));
        mx1 = fmaxf(mx1, __shfl_xor_sync(0xffffffffu, mx1, 2));

        const float mt0 = fmaxf(mrow0, mx0), mt1 = fmaxf(mrow1, mx1);
        const float fac0 = __expf(mrow0 - mt0), fac1 = __expf(mrow1 - mt1);

        // ---- exp + P hi/lo store ----
        float sum0 = 0.f, sum1 = 0.f;
#pragma unroll
        for (int nt = 0; nt < 8; nt++) {
            float p0 = __expf(s[nt][0] - mt0), p1 = __expf(s[nt][1] - mt0);
            float p2 = __expf(s[nt][2] - mt1), p3 = __expf(s[nt][3] - mt1);
            sum0 += p0 + p1; sum1 += p2 + p3;
            uint32_t hw, lw;
            split_pair(p0, p1, hw, lw);
            Ph[(m0 + lr) * 36 + nt * 4 + lc] = hw;
            Pl[(m0 + lr) * 36 + nt * 4 + lc] = lw;
            split_pair(p2, p3, hw, lw);
            Ph[(m0 + lr + 8) * 36 + nt * 4 + lc] = hw;
            Pl[(m0 + lr + 8) * 36 + nt * 4 + lc] = lw;
        }
        sum0 += __shfl_xor_sync(0xffffffffu, sum0, 1);
        sum0 += __shfl_xor_sync(0xffffffffu, sum0, 2);
        sum1 += __shfl_xor_sync(0xffffffffu, sum1, 1);
        sum1 += __shfl_xor_sync(0xffffffffu, sum1, 2);

        lrow0 = lrow0 * fac0 + sum0;
        lrow1 = lrow1 * fac1 + sum1;
        mrow0 = mt0; mrow1 = mt1;
#pragma unroll
        for (int nt = 0; nt < 16; nt++) {
            o[nt][0] *= fac0; o[nt][1] *= fac0;
            o[nt][2] *= fac1; o[nt][3] *= fac1;
        }
        __syncwarp();   // P rows are warp-private

        // ---- O += P @ V (m16 x n128 x k64), split-bf16 ----
#pragma unroll
        for (int ks = 0; ks < 4; ks++) {
            uint32_t ah[4], al[4];
            const int ab  = (m0 + lr) * 36 + ks * 8;
            const int ab8 = ab + 8 * 36;
            ah[0] = Ph[ab + lc];     ah[1] = Ph[ab8 + lc];
            ah[2] = Ph[ab + lc + 4]; ah[3] = Ph[ab8 + lc + 4];
            al[0] = Pl[ab + lc];     al[1] = Pl[ab8 + lc];
            al[2] = Pl[ab + lc + 4]; al[3] = Pl[ab8 + lc + 4];
#pragma unroll
            for (int nt = 0; nt < 16; nt++) {
                const int nb = (nt * 8 + lr) * 36 + ks * 8;
                uint32_t bh0 = Vh[nb + lc], bh1 = Vh[nb + lc + 4];
                uint32_t bl0 = Vl[nb + lc], bl1 = Vl[nb + lc + 4];
                mma_bf16(o[nt], ah, bh0, bh1);
                mma_bf16(o[nt], ah, bl0, bl1);
                mma_bf16(o[nt], al, bh0, bh1);
            }
        }
    }

    // Epilogue: normalize, split to bf16 hi/lo attn planes [s][h*128+d]
    const float inv0 = 1.f / lrow0, inv1 = 1.f / lrow1;
    uint32_t* AH = (uint32_t*)AHg;
    uint32_t* AL = (uint32_t*)ALg;
    const size_t w0 = (size_t)(qt * 128 + m0 + lr) * (DIM_ / 2) + h * 64;
    const size_t w1 = w0 + (size_t)8 * (DIM_ / 2);
#pragma unroll
    for (int nt = 0; nt < 16; nt++) {
        uint32_t hw, lw;
        split_pair(o[nt][0] * inv0, o[nt][1] * inv0, hw, lw);
        AH[w0 + nt * 4 + lc] = hw;
        AL[w0 + nt * 4 + lc] = lw;
        split_pair(o[nt][2] * inv1, o[nt][3] * inv1, hw, lw);
        AH[w1 + nt * 4 + lc] = hw;
        AL[w1 + nt * 4 + lc] = lw;
    }
}

// ---------------------------------------------------------------------------
// Launcher
// ---------------------------------------------------------------------------
static const int GEMM_SMEM  = 8 * GPS * 4;                       // 81920 B
static const int FLASH_SMEM = (2*128*68 + 2*64*68 + 4*128*36) * 4; // 178176 B

extern "C" void kernel_launch(void* const* d_in, const int* in_sizes, int n_in,
                              void* d_out, int out_size)
{
    const float* x  = (const float*)d_in[0];
    const float* wq = (const float*)d_in[1];
    const float* wk = (const float*)d_in[2];
    const float* wv = (const float*)d_in[3];
    const float* wo = (const float*)d_in[4];
    const float* fc = (const float*)d_in[5];
    const float* fs = (const float*)d_in[6];
    float* out = (float*)d_out;

    float *q, *k, *v;
    __nv_bfloat16 *xhi, *xlo, *ahi, *alo;
    __nv_bfloat16 *wqh, *wql, *wkh, *wkl, *wvh, *wvl, *woh, *wol;
    cudaGetSymbolAddress((void**)&q, g_q);
    cudaGetSymbolAddress((void**)&k, g_k);
    cudaGetSymbolAddress((void**)&v, g_v);
    cudaGetSymbolAddress((void**)&xhi, g_xhi);
    cudaGetSymbolAddress((void**)&xlo, g_xlo);
    cudaGetSymbolAddress((void**)&ahi, g_ahi);
    cudaGetSymbolAddress((void**)&alo, g_alo);
    cudaGetSymbolAddress((void**)&wqh, g_wqh);
    cudaGetSymbolAddress((void**)&wql, g_wql);
    cudaGetSymbolAddress((void**)&wkh, g_wkh);
    cudaGetSymbolAddress((void**)&wkl, g_wkl);
    cudaGetSymbolAddress((void**)&wvh, g_wvh);
    cudaGetSymbolAddress((void**)&wvl, g_wvl);
    cudaGetSymbolAddress((void**)&woh, g_woh);
    cudaGetSymbolAddress((void**)&wol, g_wol);

    cudaFuncSetAttribute(gemm_bf16x3,
                         cudaFuncAttributeMaxDynamicSharedMemorySize, GEMM_SMEM);
    cudaFuncSetAttribute(flash_attn_bf16,
                         cudaFuncAttributeMaxDynamicSharedMemorySize, FLASH_SMEM);

    // --- Prep: split x; transpose+split weights ---
    int nx = S_LEN * DIM_;
    split_kernel<<<(nx + 255) / 256, 256>>>(x, xhi, xlo, nx);
    dim3 tb(32, 8);
    wsplit_kernel<<<dim3(DIM_ / 32,       DIM_ / 32), tb>>>(wq, wqh, wql, DIM_, DIM_);
    wsplit_kernel<<<dim3((NKV*HD) / 32,   DIM_ / 32), tb>>>(wk, wkh, wkl, DIM_, NKV * HD);
    wsplit_kernel<<<dim3((NKV*HD) / 32,   DIM_ / 32), tb>>>(wv, wvh, wvl, DIM_, NKV * HD);
    wsplit_kernel<<<dim3(DIM_ / 32,       DIM_ / 32), tb>>>(wo, woh, wol, DIM_, DIM_);

    dim3 blk(256);
    // --- Projections ---
    gemm_bf16x3<<<dim3(DIM_ / 128,       S_LEN / 128), blk, GEMM_SMEM>>>(
        xhi, xlo, wqh, wql, q, S_LEN, DIM_, DIM_);
    gemm_bf16x3<<<dim3((NKV*HD) / 128,   S_LEN / 128), blk, GEMM_SMEM>>>(
        xhi, xlo, wkh, wkl, k, S_LEN, NKV * HD, DIM_);
    gemm_bf16x3<<<dim3((NKV*HD) / 128,   S_LEN / 128), blk, GEMM_SMEM>>>(
        xhi, xlo, wvh, wvl, v, S_LEN, NKV * HD, DIM_);

    // --- RoPE ---
    int totq = S_LEN * NH * 64;
    rope_kernel<<<(totq + 255) / 256, 256>>>(q, fc, fs, NH, totq);
    int totk = S_LEN * NKV * 64;
    rope_kernel<<<(totk + 255) / 256, 256>>>(k, fc, fs, NKV, totk);

    // --- Attention (writes bf16 hi/lo attn planes) ---
    flash_attn_bf16<<<dim3(S_LEN / 128, NH), blk, FLASH_SMEM>>>(q, k, v, ahi, alo);

    // --- Output projection ---
    gemm_bf16x3<<<dim3(DIM_ / 128, S_LEN / 128), blk, GEMM_SMEM>>>(
        ahi, alo, woh, wol, out, S_LEN, DIM_, DIM_);
}